// round 5
// baseline (speedup 1.0000x reference)
#include <cuda_runtime.h>
#include <math.h>

#define HID       128
#define INDIM     94
#define ROWS      128
#define NTHREADS  256
#define PITCH_H   132   // multiple of 4 for float4 alignment
#define PITCH_INV 97
#define ALPHA_C   0.1f

// shared memory layout (floats)
#define OFF_A 0
#define SZ_A  (ROWS*PITCH_H)
#define OFF_B (OFF_A+SZ_A)          // hB; also holds inv (pitch 97) before layer 2
#define SZ_B  (ROWS*PITCH_H)
#define OFF_W (OFF_B+SZ_B)
#define SZ_W  (HID*HID)
#define OFF_F (OFF_W+SZ_W)
#define SZ_F  (ROWS*9)
#define OFF_R (OFF_F+SZ_F)
#define SZ_R  (ROWS*9)
#define SMEM_FLOATS (OFF_R+SZ_R)
#define SMEM_BYTES  (SMEM_FLOATS*4)

template<int P,int Q>
__device__ __forceinline__ void jrot(float S[3][3], float V[3][3]) {
    float apq = S[P][Q];
    if (fabsf(apq) > 1e-20f) {
        float theta = (S[Q][Q] - S[P][P]) / (2.0f * apq);
        float t = copysignf(1.0f, theta) / (fabsf(theta) + sqrtf(1.0f + theta*theta));
        float c = rsqrtf(1.0f + t*t);
        float s = t * c;
        #pragma unroll
        for (int k=0;k<3;k++){ float a=S[k][P], b=S[k][Q]; S[k][P]=c*a-s*b; S[k][Q]=s*a+c*b; }
        #pragma unroll
        for (int k=0;k<3;k++){ float a=S[P][k], b=S[Q][k]; S[P][k]=c*a-s*b; S[Q][k]=s*a+c*b; }
        #pragma unroll
        for (int k=0;k<3;k++){ float a=V[k][P], b=V[k][Q]; V[k][P]=c*a-s*b; V[k][Q]=s*a+c*b; }
    }
}

template<int J>
__device__ __forceinline__ void signfix(float V[3][3]) {
    float a=V[0][J], b=V[1][J], c=V[2][J];
    float aa=fabsf(a), ab=fabsf(b), ac=fabsf(c);
    float key = (aa>=ab) ? ((aa>=ac)? a : c) : ((ab>=ac)? b : c);
    if (key < 0.0f){ V[0][J]=-a; V[1][J]=-b; V[2][J]=-c; }
}

template<int I,int J>
__device__ __forceinline__ void cswap(float* e, float V[3][3]) {
    if (e[I] < e[J]) {
        float t=e[I]; e[I]=e[J]; e[J]=t;
        #pragma unroll
        for (int k=0;k<3;k++){ float v=V[k][I]; V[k][I]=V[k][J]; V[k][J]=v; }
    }
}

__device__ __forceinline__ void stage(const float* __restrict__ g, float* __restrict__ s,
                                      int nf, int t, int nt) {
    for (int i=t*4; i<nf; i+=nt*4)
        *(float4*)(s+i) = *(const float4*)(g+i);
}

__device__ __forceinline__ float gelu_exact(float v) {
    return 0.5f * v * (1.0f + erff(v * 0.70710678118654752f));
}

// 128x128(out) = 128xK(A, smem) @ Kx128(W, smem). 256 threads, 8x8 micro-tile.
__device__ __forceinline__ void gemm_tile(const float* __restrict__ A, int pa, int K,
                                          const float* __restrict__ Wb,
                                          const float* __restrict__ bias,
                                          float* __restrict__ Out, bool act)
{
    int tid = threadIdx.x;
    int tx = tid & 15;     // col group: cols tx*8 .. tx*8+7
    int ty = tid >> 4;     // row group: rows ty*8 .. ty*8+7
    const float* Ab = A + ty*8*pa;
    const float* Wp = Wb + tx*8;

    float acc[8][8];
    #pragma unroll
    for (int i=0;i<8;i++)
        #pragma unroll
        for (int j=0;j<8;j++) acc[i][j] = 0.0f;

    #pragma unroll 2
    for (int k=0; k<K; k++) {
        float a[8];
        #pragma unroll
        for (int i=0;i<8;i++) a[i] = Ab[i*pa + k];
        float4 b0 = *(const float4*)(Wp + k*HID);
        float4 b1 = *(const float4*)(Wp + k*HID + 4);
        float b[8] = {b0.x,b0.y,b0.z,b0.w,b1.x,b1.y,b1.z,b1.w};
        #pragma unroll
        for (int i=0;i<8;i++)
            #pragma unroll
            for (int j=0;j<8;j++) acc[i][j] = fmaf(a[i], b[j], acc[i][j]);
    }

    float bb[8];
    #pragma unroll
    for (int j=0;j<8;j++) bb[j] = bias[tx*8+j];

    #pragma unroll
    for (int i=0;i<8;i++) {
        float o[8];
        #pragma unroll
        for (int j=0;j<8;j++) {
            float v = acc[i][j] + bb[j];
            o[j] = act ? gelu_exact(v) : v;
        }
        float* op = Out + (ty*8+i)*PITCH_H + tx*8;
        *(float4*)(op)   = make_float4(o[0],o[1],o[2],o[3]);
        *(float4*)(op+4) = make_float4(o[4],o[5],o[6],o[7]);
    }
}

__global__ void __launch_bounds__(NTHREADS, 1)
fproj_kernel(const float* __restrict__ Fg,
             const float* __restrict__ latw,
             const float* __restrict__ W1, const float* __restrict__ b1,
             const float* __restrict__ W2, const float* __restrict__ b2,
             const float* __restrict__ W3, const float* __restrict__ b3,
             const float* __restrict__ W4, const float* __restrict__ b4,
             const float* __restrict__ W5, const float* __restrict__ b5,
             const int* __restrict__ traj,
             float* __restrict__ out, int n)
{
    extern __shared__ float smf[];
    float* bufA = smf + OFF_A;
    float* bufB = smf + OFF_B;
    float* Wb   = smf + OFF_W;
    float* Fsm  = smf + OFF_F;
    float* Rsm  = smf + OFF_R;

    const int tid  = threadIdx.x;
    const int base = blockIdx.x * ROWS;

    // ---- Phase 1: warps 0-3 do SVD + input assembly; warps 4-7 stage W1 ----
    if (tid >= ROWS) {
        stage(W1, Wb, INDIM*HID, tid-ROWS, NTHREADS-ROWS);
    } else {
        int r = base + tid;
        float* invp = bufB + tid*PITCH_INV;
        if (r < n) {
            const float* fp = Fg + (size_t)r*9;
            float f[9];
            #pragma unroll
            for (int i=0;i<9;i++) f[i] = fp[i];

            // S = F^T F
            float S[3][3];
            #pragma unroll
            for (int i=0;i<3;i++)
                #pragma unroll
                for (int j=0;j<3;j++)
                    S[i][j] = f[0+i]*f[0+j] + f[3+i]*f[3+j] + f[6+i]*f[6+j];

            float V[3][3] = {{1,0,0},{0,1,0},{0,0,1}};
            #pragma unroll
            for (int sw=0; sw<6; sw++) {
                jrot<0,1>(S,V); jrot<0,2>(S,V); jrot<1,2>(S,V);
            }

            float e[3] = {S[0][0], S[1][1], S[2][2]};
            cswap<0,1>(e,V); cswap<0,2>(e,V); cswap<1,2>(e,V);
            signfix<0>(V); signfix<1>(V); signfix<2>(V);

            float sig[3];
            #pragma unroll
            for (int j=0;j<3;j++) sig[j] = sqrtf(fmaxf(e[j], 0.0f));

            // U[:,j] = F v_j / sigma_j
            float U[3][3];
            #pragma unroll
            for (int j=0;j<3;j++) {
                float inv_s = 1.0f / sig[j];
                #pragma unroll
                for (int i=0;i<3;i++)
                    U[i][j] = (f[3*i+0]*V[0][j] + f[3*i+1]*V[1][j] + f[3*i+2]*V[2][j]) * inv_s;
            }

            // R = U V^T
            float R[9];
            #pragma unroll
            for (int i=0;i<3;i++)
                #pragma unroll
                for (int j=0;j<3;j++)
                    R[3*i+j] = U[i][0]*V[j][0] + U[i][1]*V[j][1] + U[i][2]*V[j][2];

            // assemble inv = [F(9), U(9), sigma(3), Vh(9), lat(64)]
            #pragma unroll
            for (int i=0;i<9;i++) invp[i] = f[i];
            #pragma unroll
            for (int i=0;i<3;i++)
                #pragma unroll
                for (int j=0;j<3;j++) invp[9 + 3*i + j] = U[i][j];
            #pragma unroll
            for (int i=0;i<3;i++) invp[18+i] = sig[i];
            #pragma unroll
            for (int i=0;i<3;i++)
                #pragma unroll
                for (int j=0;j<3;j++) invp[21 + 3*i + j] = V[j][i];  // Vh[i][j] = V[j][i]

            const float* lat = latw + (size_t)traj[0] * 64;
            #pragma unroll 8
            for (int c=0;c<64;c++) invp[30+c] = lat[c];

            #pragma unroll
            for (int i=0;i<9;i++) { Fsm[tid*9+i] = f[i]; Rsm[tid*9+i] = R[i]; }
        } else {
            for (int i=0;i<INDIM;i++) invp[i] = 0.0f;
            #pragma unroll
            for (int i=0;i<9;i++) { Fsm[tid*9+i] = 0.0f; Rsm[tid*9+i] = 0.0f; }
        }
    }
    __syncthreads();

    // ---- Layer 1: inv(bufB,pitch97) @ W1 -> bufA ----
    gemm_tile(bufB, PITCH_INV, INDIM, Wb, b1, bufA, true);
    __syncthreads();

    stage(W2, Wb, HID*HID, tid, NTHREADS);
    __syncthreads();
    gemm_tile(bufA, PITCH_H, HID, Wb, b2, bufB, true);
    __syncthreads();

    stage(W3, Wb, HID*HID, tid, NTHREADS);
    __syncthreads();
    gemm_tile(bufB, PITCH_H, HID, Wb, b3, bufA, true);
    __syncthreads();

    stage(W4, Wb, HID*HID, tid, NTHREADS);
    __syncthreads();
    gemm_tile(bufA, PITCH_H, HID, Wb, b4, bufB, true);
    __syncthreads();

    stage(W5, Wb, HID*9, tid, NTHREADS);
    __syncthreads();

    // ---- Layer 5 + epilogue: one thread per row ----
    if (tid < ROWS) {
        int r = base + tid;
        if (r < n) {
            const float* h = bufB + tid*PITCH_H;
            float x[9];
            #pragma unroll
            for (int j=0;j<9;j++) x[j] = b5[j];
            #pragma unroll 4
            for (int k=0;k<HID;k++) {
                float a = h[k];
                #pragma unroll
                for (int j=0;j<9;j++) x[j] = fmaf(a, Wb[k*9+j], x[j]);
            }
            // symmetrize
            float xs[9];
            #pragma unroll
            for (int i=0;i<3;i++)
                #pragma unroll
                for (int j=0;j<3;j++)
                    xs[3*i+j] = 0.5f*(x[3*i+j] + x[3*j+i]);

            const float* R  = Rsm + tid*9;
            const float* Ff = Fsm + tid*9;
            float* op = out + (size_t)r*9;
            #pragma unroll
            for (int i=0;i<3;i++)
                #pragma unroll
                for (int j=0;j<3;j++)
                    op[3*i+j] = ALPHA_C*(R[3*i+0]*xs[0+j] + R[3*i+1]*xs[3+j] + R[3*i+2]*xs[6+j])
                                + Ff[3*i+j];
        }
    }
}

extern "C" void kernel_launch(void* const* d_in, const int* in_sizes, int n_in,
                              void* d_out, int out_size)
{
    const float* F    = (const float*)d_in[0];
    const float* latw = (const float*)d_in[1];
    const float* W1   = (const float*)d_in[2];
    const float* b1   = (const float*)d_in[3];
    const float* W2   = (const float*)d_in[4];
    const float* b2   = (const float*)d_in[5];
    const float* W3   = (const float*)d_in[6];
    const float* b3   = (const float*)d_in[7];
    const float* W4   = (const float*)d_in[8];
    const float* b4   = (const float*)d_in[9];
    const float* W5   = (const float*)d_in[10];
    const float* b5   = (const float*)d_in[11];
    const int*   traj = (const int*)d_in[12];
    float* out = (float*)d_out;

    int n = in_sizes[0] / 9;
    cudaFuncSetAttribute(fproj_kernel, cudaFuncAttributeMaxDynamicSharedMemorySize, SMEM_BYTES);
    dim3 grid((n + ROWS - 1) / ROWS);
    fproj_kernel<<<grid, NTHREADS, SMEM_BYTES>>>(F, latw, W1,b1, W2,b2, W3,b3, W4,b4, W5,b5,
                                                 traj, out, n);
}

// round 6
// speedup vs baseline: 1.9245x; 1.9245x over previous
#include <cuda_runtime.h>
#include <cuda_bf16.h>
#include <math.h>
#include <stdint.h>

#define HID       128
#define INDIM     94
#define K1PAD     96     // layer-1 K padded to 6 k-tiles
#define ROWS      128
#define NTHREADS  256
#define PB        136    // bf16 pitch for A/W smem tiles (16B-aligned rows, conflict-staggered)
#define ALPHA_C   0.1f

// ---------------- shared memory layout (bytes) ----------------
#define OFF_A0   0
#define SZ_AB    (ROWS*PB*2)            // 34816 B
#define OFF_A1   (OFF_A0 + SZ_AB)
#define OFF_W1   (OFF_A1 + SZ_AB)       // 96*136*2  = 26112
#define OFF_W2   (OFF_W1 + K1PAD*PB*2)
#define OFF_W3   (OFF_W2 + HID*PB*2)
#define OFF_W4   (OFF_W3 + HID*PB*2)
#define OFF_W5   (OFF_W4 + HID*PB*2)    // fp32 128*9 = 4608
#define OFF_F    (OFF_W5 + HID*9*4)
#define OFF_R    (OFF_F  + ROWS*9*4)
#define SMEM_BYTES (OFF_R + ROWS*9*4)   // = 214016

// ---------------- SVD helpers (fp32, unchanged) ----------------
template<int P,int Q>
__device__ __forceinline__ void jrot(float S[3][3], float V[3][3]) {
    float apq = S[P][Q];
    if (fabsf(apq) > 1e-20f) {
        float theta = (S[Q][Q] - S[P][P]) / (2.0f * apq);
        float t = copysignf(1.0f, theta) / (fabsf(theta) + sqrtf(1.0f + theta*theta));
        float c = rsqrtf(1.0f + t*t);
        float s = t * c;
        #pragma unroll
        for (int k=0;k<3;k++){ float a=S[k][P], b=S[k][Q]; S[k][P]=c*a-s*b; S[k][Q]=s*a+c*b; }
        #pragma unroll
        for (int k=0;k<3;k++){ float a=S[P][k], b=S[Q][k]; S[P][k]=c*a-s*b; S[Q][k]=s*a+c*b; }
        #pragma unroll
        for (int k=0;k<3;k++){ float a=V[k][P], b=V[k][Q]; V[k][P]=c*a-s*b; V[k][Q]=s*a+c*b; }
    }
}
template<int J>
__device__ __forceinline__ void signfix(float V[3][3]) {
    float a=V[0][J], b=V[1][J], c=V[2][J];
    float aa=fabsf(a), ab=fabsf(b), ac=fabsf(c);
    float key = (aa>=ab) ? ((aa>=ac)? a : c) : ((ab>=ac)? b : c);
    if (key < 0.0f){ V[0][J]=-a; V[1][J]=-b; V[2][J]=-c; }
}
template<int I,int J>
__device__ __forceinline__ void cswap(float* e, float V[3][3]) {
    if (e[I] < e[J]) {
        float t=e[I]; e[I]=e[J]; e[J]=t;
        #pragma unroll
        for (int k=0;k<3;k++){ float v=V[k][I]; V[k][I]=V[k][J]; V[k][J]=v; }
    }
}

// fast GELU (tanh form); clamped so __expf never overflows. |dev from exact erf| ≤ ~1e-3,
// which perturbs the final output by <1e-5 relative (x is scaled by ALPHA and tiny vs F).
__device__ __forceinline__ float gelu_f(float x) {
    float u = x * (0.7978845608f + 0.0356774081f * x * x);
    u = fmaxf(fminf(u, 10.0f), -10.0f);
    float e = __expf(-2.0f * u);
    float th = (1.0f - e) / (1.0f + e);
    return 0.5f * x * (1.0f + th);
}

// stage fp32 [K][128] global -> bf16 smem [K][PB]
__device__ __forceinline__ void stage_w(const float* __restrict__ g, __nv_bfloat16* __restrict__ s,
                                        int K, int t, int nt) {
    int total = K * HID;
    for (int i = t*4; i < total; i += nt*4) {
        float4 v = *(const float4*)(g + i);
        int k = i >> 7, nn = i & 127;
        __nv_bfloat16* d = s + k*PB + nn;
        *(__nv_bfloat162*)(d)     = __floats2bfloat162_rn(v.x, v.y);
        *(__nv_bfloat162*)(d + 2) = __floats2bfloat162_rn(v.z, v.w);
    }
}

// 128x128(out,bf16) = 128x(16*KT)(A,bf16 smem) @ (16*KT)x128(W,bf16 smem), f32 accum.
// 8 warps; warp w owns rows 16w..16w+15, all 128 cols. mma.sync m16n8k16 bf16.
template<int KT, bool ACT>
__device__ __forceinline__ void gemm_mma(const __nv_bfloat16* __restrict__ A,
                                         const __nv_bfloat16* __restrict__ W,
                                         const float* __restrict__ bias,
                                         __nv_bfloat16* __restrict__ Out)
{
    const int warp = threadIdx.x >> 5;
    const int lane = threadIdx.x & 31;

    float acc[16][4];
    #pragma unroll
    for (int t=0;t<16;t++){ acc[t][0]=0.f; acc[t][1]=0.f; acc[t][2]=0.f; acc[t][3]=0.f; }

    uint32_t aAddr = (uint32_t)__cvta_generic_to_shared(
        A + (warp*16 + (lane & 15))*PB + ((lane >> 4) << 3));
    uint32_t wAddr = (uint32_t)__cvta_generic_to_shared(
        W + (lane & 15)*PB);

    #pragma unroll
    for (int kb=0; kb<KT; kb++) {
        uint32_t a0,a1,a2,a3;
        asm volatile("ldmatrix.sync.aligned.m8n8.x4.shared.b16 {%0,%1,%2,%3},[%4];"
            : "=r"(a0),"=r"(a1),"=r"(a2),"=r"(a3) : "r"(aAddr + kb*32));
        #pragma unroll
        for (int t=0;t<16;t++) {
            uint32_t b0,b1;
            asm volatile("ldmatrix.sync.aligned.m8n8.x2.trans.shared.b16 {%0,%1},[%2];"
                : "=r"(b0),"=r"(b1) : "r"(wAddr + (uint32_t)((kb*16*PB + 8*t)*2)));
            asm volatile("mma.sync.aligned.m16n8k16.row.col.f32.bf16.bf16.f32 "
                "{%0,%1,%2,%3},{%4,%5,%6,%7},{%8,%9},{%0,%1,%2,%3};"
                : "+f"(acc[t][0]),"+f"(acc[t][1]),"+f"(acc[t][2]),"+f"(acc[t][3])
                : "r"(a0),"r"(a1),"r"(a2),"r"(a3),"r"(b0),"r"(b1));
        }
    }

    const int g  = lane >> 2;
    const int c4 = lane & 3;
    const int r0 = warp*16 + g;
    #pragma unroll
    for (int t=0;t<16;t++) {
        int col = t*8 + c4*2;
        float2 bb = *(const float2*)(bias + col);
        float v0 = acc[t][0] + bb.x;
        float v1 = acc[t][1] + bb.y;
        float v2 = acc[t][2] + bb.x;
        float v3 = acc[t][3] + bb.y;
        if (ACT) { v0 = gelu_f(v0); v1 = gelu_f(v1); v2 = gelu_f(v2); v3 = gelu_f(v3); }
        *(__nv_bfloat162*)(Out + r0*PB + col)       = __floats2bfloat162_rn(v0, v1);
        *(__nv_bfloat162*)(Out + (r0+8)*PB + col)   = __floats2bfloat162_rn(v2, v3);
    }
}

__global__ void __launch_bounds__(NTHREADS, 1)
fproj_kernel(const float* __restrict__ Fg,
             const float* __restrict__ latw,
             const float* __restrict__ W1, const float* __restrict__ b1,
             const float* __restrict__ W2, const float* __restrict__ b2,
             const float* __restrict__ W3, const float* __restrict__ b3,
             const float* __restrict__ W4, const float* __restrict__ b4,
             const float* __restrict__ W5, const float* __restrict__ b5,
             const int* __restrict__ traj,
             float* __restrict__ out, int n)
{
    extern __shared__ __align__(16) unsigned char smraw[];
    __nv_bfloat16* A0  = (__nv_bfloat16*)(smraw + OFF_A0);
    __nv_bfloat16* A1  = (__nv_bfloat16*)(smraw + OFF_A1);
    __nv_bfloat16* W1s = (__nv_bfloat16*)(smraw + OFF_W1);
    __nv_bfloat16* W2s = (__nv_bfloat16*)(smraw + OFF_W2);
    __nv_bfloat16* W3s = (__nv_bfloat16*)(smraw + OFF_W3);
    __nv_bfloat16* W4s = (__nv_bfloat16*)(smraw + OFF_W4);
    float*         W5s = (float*)(smraw + OFF_W5);
    float*         Fsm = (float*)(smraw + OFF_F);
    float*         Rsm = (float*)(smraw + OFF_R);

    const int tid  = threadIdx.x;
    const int base = blockIdx.x * ROWS;

    // ---- Phase 1: threads 0-127 SVD + input assembly; threads 128-255 stage all weights ----
    if (tid >= ROWS) {
        int t = tid - ROWS;
        stage_w(W1, W1s, INDIM, t, ROWS);
        // zero pad rows 94,95 of W1 (k-padding; A pad cols are zero but avoid NaN from 0*garbage)
        for (int i = t; i < 2*HID; i += ROWS) {
            int k = INDIM + (i >> 7), nn = i & 127;
            W1s[k*PB + nn] = __float2bfloat16(0.0f);
        }
        stage_w(W2, W2s, HID, t, ROWS);
        stage_w(W3, W3s, HID, t, ROWS);
        stage_w(W4, W4s, HID, t, ROWS);
        for (int i = t; i < HID*9; i += ROWS) W5s[i] = W5[i];
    } else {
        int r = base + tid;
        __nv_bfloat16* invp = A0 + tid*PB;
        if (r < n) {
            const float* fp = Fg + (size_t)r*9;
            float f[9];
            #pragma unroll
            for (int i=0;i<9;i++) f[i] = fp[i];

            float S[3][3];
            #pragma unroll
            for (int i=0;i<3;i++)
                #pragma unroll
                for (int j=0;j<3;j++)
                    S[i][j] = f[0+i]*f[0+j] + f[3+i]*f[3+j] + f[6+i]*f[6+j];

            float V[3][3] = {{1,0,0},{0,1,0},{0,0,1}};
            #pragma unroll
            for (int sw=0; sw<6; sw++) { jrot<0,1>(S,V); jrot<0,2>(S,V); jrot<1,2>(S,V); }

            float e[3] = {S[0][0], S[1][1], S[2][2]};
            cswap<0,1>(e,V); cswap<0,2>(e,V); cswap<1,2>(e,V);
            signfix<0>(V); signfix<1>(V); signfix<2>(V);

            float sig[3];
            #pragma unroll
            for (int j=0;j<3;j++) sig[j] = sqrtf(fmaxf(e[j], 0.0f));

            float U[3][3];
            #pragma unroll
            for (int j=0;j<3;j++) {
                float inv_s = 1.0f / sig[j];
                #pragma unroll
                for (int i=0;i<3;i++)
                    U[i][j] = (f[3*i+0]*V[0][j] + f[3*i+1]*V[1][j] + f[3*i+2]*V[2][j]) * inv_s;
            }

            float R[9];
            #pragma unroll
            for (int i=0;i<3;i++)
                #pragma unroll
                for (int j=0;j<3;j++)
                    R[3*i+j] = U[i][0]*V[j][0] + U[i][1]*V[j][1] + U[i][2]*V[j][2];

            // inv = [F(9), U(9), sigma(3), Vh(9), lat(64)], bf16, cols 94-95 zero
            #pragma unroll
            for (int i=0;i<9;i++) invp[i] = __float2bfloat16(f[i]);
            #pragma unroll
            for (int i=0;i<3;i++)
                #pragma unroll
                for (int j=0;j<3;j++) invp[9 + 3*i + j] = __float2bfloat16(U[i][j]);
            #pragma unroll
            for (int i=0;i<3;i++) invp[18+i] = __float2bfloat16(sig[i]);
            #pragma unroll
            for (int i=0;i<3;i++)
                #pragma unroll
                for (int j=0;j<3;j++) invp[21 + 3*i + j] = __float2bfloat16(V[j][i]);

            const float* lat = latw + (size_t)traj[0] * 64;
            #pragma unroll 8
            for (int c=0;c<64;c++) invp[30+c] = __float2bfloat16(lat[c]);
            invp[94] = __float2bfloat16(0.0f);
            invp[95] = __float2bfloat16(0.0f);

            #pragma unroll
            for (int i=0;i<9;i++) { Fsm[tid*9+i] = f[i]; Rsm[tid*9+i] = R[i]; }
        } else {
            for (int i=0;i<K1PAD;i++) invp[i] = __float2bfloat16(0.0f);
            #pragma unroll
            for (int i=0;i<9;i++) { Fsm[tid*9+i] = 0.0f; Rsm[tid*9+i] = 0.0f; }
        }
    }
    __syncthreads();

    // ---- MLP layers 1-4 on tensor cores ----
    gemm_mma<6, true>(A0, W1s, b1, A1);  __syncthreads();
    gemm_mma<8, true>(A1, W2s, b2, A0);  __syncthreads();
    gemm_mma<8, true>(A0, W3s, b3, A1);  __syncthreads();
    gemm_mma<8, true>(A1, W4s, b4, A0);  __syncthreads();

    // ---- Layer 5 (128->9, fp32) + symmetrize + R*x + F epilogue: one thread per row ----
    if (tid < ROWS) {
        int r = base + tid;
        if (r < n) {
            const __nv_bfloat16* h = A0 + tid*PB;
            float x[9];
            #pragma unroll
            for (int j=0;j<9;j++) x[j] = b5[j];
            #pragma unroll 4
            for (int k=0;k<HID;k++) {
                float a = __bfloat162float(h[k]);
                #pragma unroll
                for (int j=0;j<9;j++) x[j] = fmaf(a, W5s[k*9+j], x[j]);
            }
            float xs[9];
            #pragma unroll
            for (int i=0;i<3;i++)
                #pragma unroll
                for (int j=0;j<3;j++)
                    xs[3*i+j] = 0.5f*(x[3*i+j] + x[3*j+i]);

            const float* R  = Rsm + tid*9;
            const float* Ff = Fsm + tid*9;
            float* op = out + (size_t)r*9;
            #pragma unroll
            for (int i=0;i<3;i++)
                #pragma unroll
                for (int j=0;j<3;j++)
                    op[3*i+j] = ALPHA_C*(R[3*i+0]*xs[0+j] + R[3*i+1]*xs[3+j] + R[3*i+2]*xs[6+j])
                                + Ff[3*i+j];
        }
    }
}

extern "C" void kernel_launch(void* const* d_in, const int* in_sizes, int n_in,
                              void* d_out, int out_size)
{
    const float* F    = (const float*)d_in[0];
    const float* latw = (const float*)d_in[1];
    const float* W1   = (const float*)d_in[2];
    const float* b1   = (const float*)d_in[3];
    const float* W2   = (const float*)d_in[4];
    const float* b2   = (const float*)d_in[5];
    const float* W3   = (const float*)d_in[6];
    const float* b3   = (const float*)d_in[7];
    const float* W4   = (const float*)d_in[8];
    const float* b4   = (const float*)d_in[9];
    const float* W5   = (const float*)d_in[10];
    const float* b5   = (const float*)d_in[11];
    const int*   traj = (const int*)d_in[12];
    float* out = (float*)d_out;

    int n = in_sizes[0] / 9;
    cudaFuncSetAttribute(fproj_kernel, cudaFuncAttributeMaxDynamicSharedMemorySize, SMEM_BYTES);
    dim3 grid((n + ROWS - 1) / ROWS);
    fproj_kernel<<<grid, NTHREADS, SMEM_BYTES>>>(F, latw, W1,b1, W2,b2, W3,b3, W4,b4, W5,b5,
                                                 traj, out, n);
}

// round 8
// speedup vs baseline: 6.7183x; 3.4910x over previous
#include <cuda_runtime.h>
#include <cuda_bf16.h>
#include <math.h>
#include <stdint.h>

#define HID       128
#define INDIM     94
#define K1PAD     96
#define ROWS      256      // rows per tile
#define NTHREADS  512      // 16 warps
#define PB        136      // bf16 smem pitch
#define ALPHA_C   0.1f

// ---------------- shared memory layout (bytes) ----------------
#define OFF_A0   0
#define OFF_W1   (OFF_A0 + ROWS*PB*2)        // 69632
#define OFF_W2   (OFF_W1 + K1PAD*PB*2)       // +26112
#define OFF_W3   (OFF_W2 + HID*PB*2)         // +34816
#define OFF_W4   (OFF_W3 + HID*PB*2)
#define OFF_W5   (OFF_W4 + HID*PB*2)         // fp32 128*9
#define OFF_BIAS (OFF_W5 + HID*9*4)          // b1..b4 (512) + b5 (9) + pad
#define OFF_F    (OFF_BIAS + (4*HID+16)*4)
#define OFF_R    (OFF_F + ROWS*9*4)
#define SMEM_BYTES (OFF_R + ROWS*9*4)        // 225344 <= 232448

// ---------------- SVD helpers ----------------
template<int P,int Q>
__device__ __forceinline__ void jrot(float S[3][3], float V[3][3]) {
    float apq = S[P][Q];
    if (fabsf(apq) > 1e-20f) {
        float theta = (S[Q][Q] - S[P][P]) / (2.0f * apq);
        float t = copysignf(1.0f, theta) / (fabsf(theta) + sqrtf(1.0f + theta*theta));
        float c = rsqrtf(1.0f + t*t);
        float s = t * c;
        #pragma unroll
        for (int k=0;k<3;k++){ float a=S[k][P], b=S[k][Q]; S[k][P]=c*a-s*b; S[k][Q]=s*a+c*b; }
        #pragma unroll
        for (int k=0;k<3;k++){ float a=S[P][k], b=S[Q][k]; S[P][k]=c*a-s*b; S[P][k]=c*a-s*b; S[P][k]=c*a-s*b; S[P][k]=c*a-s*b; S[P][k]=c*a-s*b; S[P][k]=c*a-s*b; S[P][k]=c*a-s*b; S[P][k]=c*a-s*b; }
    }
}
// NOTE: corrected clean version below (the above is wrong); real one used:
template<int P,int Q>
__device__ __forceinline__ void jrot2(float S[3][3], float V[3][3]) {
    float apq = S[P][Q];
    if (fabsf(apq) > 1e-20f) {
        float theta = (S[Q][Q] - S[P][P]) / (2.0f * apq);
        float t = copysignf(1.0f, theta) / (fabsf(theta) + sqrtf(1.0f + theta*theta));
        float c = rsqrtf(1.0f + t*t);
        float s = t * c;
        #pragma unroll
        for (int k=0;k<3;k++){ float a=S[k][P], b=S[k][Q]; S[k][P]=c*a-s*b; S[k][Q]=s*a+c*b; }
        #pragma unroll
        for (int k=0;k<3;k++){ float a=S[P][k], b=S[Q][k]; S[P][k]=c*a-s*b; S[Q][k]=s*a+c*b; }
        #pragma unroll
        for (int k=0;k<3;k++){ float a=V[k][P], b=V[k][Q]; V[k][P]=c*a-s*b; V[k][Q]=s*a+c*b; }
    }
}
template<int J>
__device__ __forceinline__ void signfix(float V[3][3]) {
    float a=V[0][J], b=V[1][J], c=V[2][J];
    float aa=fabsf(a), ab=fabsf(b), ac=fabsf(c);
    float key = (aa>=ab) ? ((aa>=ac)? a : c) : ((ab>=ac)? b : c);
    if (key < 0.0f){ V[0][J]=-a; V[1][J]=-b; V[2][J]=-c; }
}
template<int I,int J>
__device__ __forceinline__ void cswap(float* e, float V[3][3]) {
    if (e[I] < e[J]) {
        float t=e[I]; e[I]=e[J]; e[J]=t;
        #pragma unroll
        for (int k=0;k<3;k++){ float v=V[k][I]; V[k][I]=V[k][J]; V[k][J]=v; }
    }
}

__device__ __forceinline__ float gelu_f(float x) {
    float u = x * (0.7978845608f + 0.0356774081f * x * x);
    float th;
    asm("tanh.approx.f32 %0, %1;" : "=f"(th) : "f"(u));
    return 0.5f * x * (1.0f + th);
}

// stage fp32 [K][128] global -> bf16 smem [K][PB]
__device__ __forceinline__ void stage_w(const float* __restrict__ g, __nv_bfloat16* __restrict__ s,
                                        int K, int t, int nt) {
    int total = K * HID;
    for (int i = t*4; i < total; i += nt*4) {
        float4 v = *(const float4*)(g + i);
        int k = i >> 7, nn = i & 127;
        __nv_bfloat16* d = s + k*PB + nn;
        *(__nv_bfloat162*)(d)     = __floats2bfloat162_rn(v.x, v.y);
        *(__nv_bfloat162*)(d + 2) = __floats2bfloat162_rn(v.z, v.w);
    }
}

// In-place GEMM: A[256 x 16*KT] @ W[16*KT x 128] -> A[256 x 128], bf16 in/out, f32 acc.
// 16 warps; warp w owns rows 16w..16w+15. All A-frags preloaded -> in-place safe.
// No block barrier needed (each warp reads/writes only its own rows); __syncwarp at end.
template<int KT, bool ACT>
__device__ __forceinline__ void gemm_mma(__nv_bfloat16* __restrict__ A,
                                         const __nv_bfloat16* __restrict__ W,
                                         const float* __restrict__ bias)
{
    const int warp = threadIdx.x >> 5;
    const int lane = threadIdx.x & 31;

    uint32_t aAddr = (uint32_t)__cvta_generic_to_shared(
        A + (warp*16 + (lane & 15))*PB + ((lane >> 4) << 3));
    uint32_t wBase = (uint32_t)__cvta_generic_to_shared(W)
        + (uint32_t)(((lane & 15)*PB + ((lane >> 4) << 3)) * 2);

    // preload all A fragments (needed for in-place update)
    uint32_t af[KT][4];
    #pragma unroll
    for (int kb=0; kb<KT; kb++)
        asm volatile("ldmatrix.sync.aligned.m8n8.x4.shared.b16 {%0,%1,%2,%3},[%4];"
            : "=r"(af[kb][0]),"=r"(af[kb][1]),"=r"(af[kb][2]),"=r"(af[kb][3])
            : "r"(aAddr + kb*32));

    float acc[16][4];
    #pragma unroll
    for (int t=0;t<16;t++){ acc[t][0]=0.f; acc[t][1]=0.f; acc[t][2]=0.f; acc[t][3]=0.f; }

    #pragma unroll
    for (int tp=0; tp<8; tp++) {
        #pragma unroll
        for (int kb=0; kb<KT; kb++) {
            uint32_t b0,b1,b2,b3;
            asm volatile("ldmatrix.sync.aligned.m8n8.x4.trans.shared.b16 {%0,%1,%2,%3},[%4];"
                : "=r"(b0),"=r"(b1),"=r"(b2),"=r"(b3)
                : "r"(wBase + (uint32_t)((kb*16*PB + 16*tp)*2)));
            asm volatile("mma.sync.aligned.m16n8k16.row.col.f32.bf16.bf16.f32 "
                "{%0,%1,%2,%3},{%4,%5,%6,%7},{%8,%9},{%0,%1,%2,%3};"
                : "+f"(acc[2*tp][0]),"+f"(acc[2*tp][1]),"+f"(acc[2*tp][2]),"+f"(acc[2*tp][3])
                : "r"(af[kb][0]),"r"(af[kb][1]),"r"(af[kb][2]),"r"(af[kb][3]),"r"(b0),"r"(b1));
            asm volatile("mma.sync.aligned.m16n8k16.row.col.f32.bf16.bf16.f32 "
                "{%0,%1,%2,%3},{%4,%5,%6,%7},{%8,%9},{%0,%1,%2,%3};"
                : "+f"(acc[2*tp+1][0]),"+f"(acc[2*tp+1][1]),"+f"(acc[2*tp+1][2]),"+f"(acc[2*tp+1][3])
                : "r"(af[kb][0]),"r"(af[kb][1]),"r"(af[kb][2]),"r"(af[kb][3]),"r"(b2),"r"(b3));
        }
    }

    const int g  = lane >> 2;
    const int c4 = lane & 3;
    const int r0 = warp*16 + g;
    #pragma unroll
    for (int t=0;t<16;t++) {
        int col = t*8 + c4*2;
        float2 bb = *(const float2*)(bias + col);
        float v0 = acc[t][0] + bb.x;
        float v1 = acc[t][1] + bb.y;
        float v2 = acc[t][2] + bb.x;
        float v3 = acc[t][3] + bb.y;
        if (ACT) { v0 = gelu_f(v0); v1 = gelu_f(v1); v2 = gelu_f(v2); v3 = gelu_f(v3); }
        *(__nv_bfloat162*)(A + r0*PB + col)     = __floats2bfloat162_rn(v0, v1);
        *(__nv_bfloat162*)(A + (r0+8)*PB + col) = __floats2bfloat162_rn(v2, v3);
    }
    __syncwarp();
}

__global__ void __launch_bounds__(NTHREADS, 1)
fproj_kernel(const float* __restrict__ Fg,
             const float* __restrict__ latw,
             const float* __restrict__ W1, const float* __restrict__ b1,
             const float* __restrict__ W2, const float* __restrict__ b2,
             const float* __restrict__ W3, const float* __restrict__ b3,
             const float* __restrict__ W4, const float* __restrict__ b4,
             const float* __restrict__ W5, const float* __restrict__ b5,
             const int* __restrict__ traj,
             float* __restrict__ out, int n, int ntiles)
{
    extern __shared__ __align__(16) unsigned char smraw[];
    __nv_bfloat16* A0  = (__nv_bfloat16*)(smraw + OFF_A0);
    __nv_bfloat16* W1s = (__nv_bfloat16*)(smraw + OFF_W1);
    __nv_bfloat16* W2s = (__nv_bfloat16*)(smraw + OFF_W2);
    __nv_bfloat16* W3s = (__nv_bfloat16*)(smraw + OFF_W3);
    __nv_bfloat16* W4s = (__nv_bfloat16*)(smraw + OFF_W4);
    float*         W5s = (float*)(smraw + OFF_W5);
    float*         bsm = (float*)(smraw + OFF_BIAS);
    float*         Fsm = (float*)(smraw + OFF_F);
    float*         Rsm = (float*)(smraw + OFF_R);

    const int tid = threadIdx.x;

    // ---- one-time weight staging (all 512 threads) ----
    stage_w(W1, W1s, INDIM, tid, NTHREADS);
    for (int i = tid; i < 2*HID; i += NTHREADS) {            // zero-pad W1 rows 94,95
        int k = INDIM + (i >> 7), nn = i & 127;
        W1s[k*PB + nn] = __float2bfloat16(0.0f);
    }
    stage_w(W2, W2s, HID, tid, NTHREADS);
    stage_w(W3, W3s, HID, tid, NTHREADS);
    stage_w(W4, W4s, HID, tid, NTHREADS);
    for (int i = tid; i < HID*9; i += NTHREADS) W5s[i] = W5[i];
    if (tid < HID)      bsm[tid]       = b1[tid];
    else if (tid < 2*HID) bsm[tid]     = b2[tid-HID];
    else if (tid < 3*HID) bsm[tid]     = b3[tid-2*HID];
    else if (tid < 4*HID) bsm[tid]     = b4[tid-3*HID];
    if (tid < 9) bsm[4*HID + tid] = b5[tid];
    const float* latp = latw + (size_t)traj[0] * 64;
    __syncthreads();

    // ---- persistent tile loop ----
    for (int tile = blockIdx.x; tile < ntiles; tile += gridDim.x) {
        const int base = tile * ROWS;

        // Phase 1: threads 0-255 -> SVD + input assembly for row (base+tid)
        if (tid < ROWS) {
            int r = base + tid;
            __nv_bfloat16* invp = A0 + tid*PB;
            if (r < n) {
                const float* fp = Fg + (size_t)r*9;
                float f[9];
                #pragma unroll
                for (int i=0;i<9;i++) f[i] = fp[i];

                float S[3][3];
                #pragma unroll
                for (int i=0;i<3;i++)
                    #pragma unroll
                    for (int j=0;j<3;j++)
                        S[i][j] = f[0+i]*f[0+j] + f[3+i]*f[3+j] + f[6+i]*f[6+j];

                float V[3][3] = {{1,0,0},{0,1,0},{0,0,1}};
                #pragma unroll
                for (int sw=0; sw<6; sw++) { jrot2<0,1>(S,V); jrot2<0,2>(S,V); jrot2<1,2>(S,V); }

                float e[3] = {S[0][0], S[1][1], S[2][2]};
                cswap<0,1>(e,V); cswap<0,2>(e,V); cswap<1,2>(e,V);
                signfix<0>(V); signfix<1>(V); signfix<2>(V);

                float sig[3];
                #pragma unroll
                for (int j=0;j<3;j++) sig[j] = sqrtf(fmaxf(e[j], 0.0f));

                float U[3][3];
                #pragma unroll
                for (int j=0;j<3;j++) {
                    float inv_s = 1.0f / sig[j];
                    #pragma unroll
                    for (int i=0;i<3;i++)
                        U[i][j] = (f[3*i+0]*V[0][j] + f[3*i+1]*V[1][j] + f[3*i+2]*V[2][j]) * inv_s;
                }

                float R[9];
                #pragma unroll
                for (int i=0;i<3;i++)
                    #pragma unroll
                    for (int j=0;j<3;j++)
                        R[3*i+j] = U[i][0]*V[j][0] + U[i][1]*V[j][1] + U[i][2]*V[j][2];

                #pragma unroll
                for (int i=0;i<9;i++) invp[i] = __float2bfloat16(f[i]);
                #pragma unroll
                for (int i=0;i<3;i++)
                    #pragma unroll
                    for (int j=0;j<3;j++) invp[9 + 3*i + j] = __float2bfloat16(U[i][j]);
                #pragma unroll
                for (int i=0;i<3;i++) invp[18+i] = __float2bfloat16(sig[i]);
                #pragma unroll
                for (int i=0;i<3;i++)
                    #pragma unroll
                    for (int j=0;j<3;j++) invp[21 + 3*i + j] = __float2bfloat16(V[j][i]);
                #pragma unroll 8
                for (int c=0;c<64;c++) invp[30+c] = __float2bfloat16(latp[c]);
                invp[94] = __float2bfloat16(0.0f);
                invp[95] = __float2bfloat16(0.0f);

                #pragma unroll
                for (int i=0;i<9;i++) { Fsm[tid*9+i] = f[i]; Rsm[tid*9+i] = R[i]; }
            } else {
                for (int i=0;i<K1PAD;i++) invp[i] = __float2bfloat16(0.0f);
            }
        }
        __syncthreads();

        // Layers 1-4: barrier-free (in-place, warp-private rows)
        gemm_mma<6, true>(A0, W1s, bsm);
        gemm_mma<8, true>(A0, W2s, bsm + HID);
        gemm_mma<8, true>(A0, W3s, bsm + 2*HID);
        gemm_mma<8, true>(A0, W4s, bsm + 3*HID);
        __syncthreads();

        // Layer 5 + symmetrize + R*x + F epilogue (thread t -> row t)
        if (tid < ROWS) {
            int r = base + tid;
            if (r < n) {
                const __nv_bfloat16* h = A0 + tid*PB;
                const float* b5s = bsm + 4*HID;
                float x[9];
                #pragma unroll
                for (int j=0;j<9;j++) x[j] = b5s[j];
                #pragma unroll 4
                for (int k2=0;k2<HID/2;k2++) {
                    __nv_bfloat162 hv = *(const __nv_bfloat162*)(h + 2*k2);
                    float a0 = __bfloat162float(hv.x);
                    float a1 = __bfloat162float(hv.y);
                    const float* w0 = W5s + (2*k2)*9;
                    #pragma unroll
                    for (int j=0;j<9;j++) x[j] = fmaf(a0, w0[j], x[j]);
                    #pragma unroll
                    for (int j=0;j<9;j++) x[j] = fmaf(a1, w0[9+j], x[j]);
                }
                float xs[9];
                #pragma unroll
                for (int i=0;i<3;i++)
                    #pragma unroll
                    for (int j=0;j<3;j++)
                        xs[3*i+j] = 0.5f*(x[3*i+j] + x[3*j+i]);

                const float* R  = Rsm + tid*9;
                const float* Ff = Fsm + tid*9;
                float* op = out + (size_t)r*9;
                #pragma unroll
                for (int i=0;i<3;i++)
                    #pragma unroll
                    for (int j=0;j<3;j++)
                        op[3*i+j] = ALPHA_C*(R[3*i+0]*xs[0+j] + R[3*i+1]*xs[3+j] + R[3*i+2]*xs[6+j])
                                    + Ff[3*i+j];
            }
        }
        // no barrier needed: rows/F/R are thread-private between epilogue and next phase-1;
        // post-phase-1 barrier protects the GEMM reads.
    }
}

extern "C" void kernel_launch(void* const* d_in, const int* in_sizes, int n_in,
                              void* d_out, int out_size)
{
    const float* F    = (const float*)d_in[0];
    const float* latw = (const float*)d_in[1];
    const float* W1   = (const float*)d_in[2];
    const float* b1   = (const float*)d_in[3];
    const float* W2   = (const float*)d_in[4];
    const float* b2   = (const float*)d_in[5];
    const float* W3   = (const float*)d_in[6];
    const float* b3   = (const float*)d_in[7];
    const float* W4   = (const float*)d_in[8];
    const float* b4   = (const float*)d_in[9];
    const float* W5   = (const float*)d_in[10];
    const float* b5   = (const float*)d_in[11];
    const int*   traj = (const int*)d_in[12];
    float* out = (float*)d_out;

    int n = in_sizes[0] / 9;
    int ntiles = (n + ROWS - 1) / ROWS;

    int sms = 148;
    cudaDeviceGetAttribute(&sms, cudaDevAttrMultiProcessorCount, 0);
    int grid = sms < ntiles ? sms : ntiles;

    cudaFuncSetAttribute(fproj_kernel, cudaFuncAttributeMaxDynamicSharedMemorySize, SMEM_BYTES);
    fproj_kernel<<<grid, NTHREADS, SMEM_BYTES>>>(F, latw, W1,b1, W2,b2, W3,b3, W4,b4, W5,b5,
                                                 traj, out, n, ntiles);
}

// round 9
// speedup vs baseline: 6.7473x; 1.0043x over previous
#include <cuda_runtime.h>
#include <cuda_bf16.h>
#include <math.h>
#include <stdint.h>

#define HID       128
#define INDIM     94
#define K1PAD     96
#define ROWS      256      // rows per tile
#define NTHREADS  512      // 16 warps
#define PB        136      // bf16 smem pitch
#define ALPHA_C   0.1f

// ---------------- shared memory layout (bytes) ----------------
#define OFF_A0   0
#define OFF_W1   (OFF_A0 + ROWS*PB*2)        // 69632
#define OFF_W2   (OFF_W1 + K1PAD*PB*2)       // +26112
#define OFF_W3   (OFF_W2 + HID*PB*2)         // +34816
#define OFF_W4   (OFF_W3 + HID*PB*2)
#define OFF_W5   (OFF_W4 + HID*PB*2)         // fp32 128*9
#define OFF_BIAS (OFF_W5 + HID*9*4)          // b1..b4 (512) + b5 (9) + pad
#define OFF_F    (OFF_BIAS + (4*HID+16)*4)
#define OFF_R    (OFF_F + ROWS*9*4)
#define SMEM_BYTES (OFF_R + ROWS*9*4)        // 225344 <= 232448

// ---------------- SVD helpers ----------------
template<int P,int Q>
__device__ __forceinline__ void jrot(float S[3][3], float V[3][3]) {
    float apq = S[P][Q];
    if (fabsf(apq) > 1e-20f) {
        float theta = (S[Q][Q] - S[P][P]) / (2.0f * apq);
        float t = copysignf(1.0f, theta) / (fabsf(theta) + sqrtf(1.0f + theta*theta));
        float c = rsqrtf(1.0f + t*t);
        float s = t * c;
        #pragma unroll
        for (int k=0;k<3;k++){ float a=S[k][P], b=S[k][Q]; S[k][P]=c*a-s*b; S[k][Q]=s*a+c*b; }
        #pragma unroll
        for (int k=0;k<3;k++){ float a=S[P][k], b=S[Q][k]; S[P][k]=c*a-s*b; S[P][k]=c*a-s*b; S[P][k]=c*a-s*b; S[P][k]=c*a-s*b; S[P][k]=c*a-s*b; S[P][k]=c*a-s*b; S[P][k]=c*a-s*b; S[P][k]=c*a-s*b; }
    }
}
// NOTE: corrected clean version below (the above is wrong); real one used:
template<int P,int Q>
__device__ __forceinline__ void jrot2(float S[3][3], float V[3][3]) {
    float apq = S[P][Q];
    if (fabsf(apq) > 1e-20f) {
        float theta = (S[Q][Q] - S[P][P]) / (2.0f * apq);
        float t = copysignf(1.0f, theta) / (fabsf(theta) + sqrtf(1.0f + theta*theta));
        float c = rsqrtf(1.0f + t*t);
        float s = t * c;
        #pragma unroll
        for (int k=0;k<3;k++){ float a=S[k][P], b=S[k][Q]; S[k][P]=c*a-s*b; S[k][Q]=s*a+c*b; }
        #pragma unroll
        for (int k=0;k<3;k++){ float a=S[P][k], b=S[Q][k]; S[P][k]=c*a-s*b; S[Q][k]=s*a+c*b; }
        #pragma unroll
        for (int k=0;k<3;k++){ float a=V[k][P], b=V[k][Q]; V[k][P]=c*a-s*b; V[k][Q]=s*a+c*b; }
    }
}
template<int J>
__device__ __forceinline__ void signfix(float V[3][3]) {
    float a=V[0][J], b=V[1][J], c=V[2][J];
    float aa=fabsf(a), ab=fabsf(b), ac=fabsf(c);
    float key = (aa>=ab) ? ((aa>=ac)? a : c) : ((ab>=ac)? b : c);
    if (key < 0.0f){ V[0][J]=-a; V[1][J]=-b; V[2][J]=-c; }
}
template<int I,int J>
__device__ __forceinline__ void cswap(float* e, float V[3][3]) {
    if (e[I] < e[J]) {
        float t=e[I]; e[I]=e[J]; e[J]=t;
        #pragma unroll
        for (int k=0;k<3;k++){ float v=V[k][I]; V[k][I]=V[k][J]; V[k][J]=v; }
    }
}

__device__ __forceinline__ float gelu_f(float x) {
    float u = x * (0.7978845608f + 0.0356774081f * x * x);
    float th;
    asm("tanh.approx.f32 %0, %1;" : "=f"(th) : "f"(u));
    return 0.5f * x * (1.0f + th);
}

// stage fp32 [K][128] global -> bf16 smem [K][PB]
__device__ __forceinline__ void stage_w(const float* __restrict__ g, __nv_bfloat16* __restrict__ s,
                                        int K, int t, int nt) {
    int total = K * HID;
    for (int i = t*4; i < total; i += nt*4) {
        float4 v = *(const float4*)(g + i);
        int k = i >> 7, nn = i & 127;
        __nv_bfloat16* d = s + k*PB + nn;
        *(__nv_bfloat162*)(d)     = __floats2bfloat162_rn(v.x, v.y);
        *(__nv_bfloat162*)(d + 2) = __floats2bfloat162_rn(v.z, v.w);
    }
}

// In-place GEMM: A[256 x 16*KT] @ W[16*KT x 128] -> A[256 x 128], bf16 in/out, f32 acc.
// 16 warps; warp w owns rows 16w..16w+15. All A-frags preloaded -> in-place safe.
// No block barrier needed (each warp reads/writes only its own rows); __syncwarp at end.
template<int KT, bool ACT>
__device__ __forceinline__ void gemm_mma(__nv_bfloat16* __restrict__ A,
                                         const __nv_bfloat16* __restrict__ W,
                                         const float* __restrict__ bias)
{
    const int warp = threadIdx.x >> 5;
    const int lane = threadIdx.x & 31;

    uint32_t aAddr = (uint32_t)__cvta_generic_to_shared(
        A + (warp*16 + (lane & 15))*PB + ((lane >> 4) << 3));
    uint32_t wBase = (uint32_t)__cvta_generic_to_shared(W)
        + (uint32_t)(((lane & 15)*PB + ((lane >> 4) << 3)) * 2);

    // preload all A fragments (needed for in-place update)
    uint32_t af[KT][4];
    #pragma unroll
    for (int kb=0; kb<KT; kb++)
        asm volatile("ldmatrix.sync.aligned.m8n8.x4.shared.b16 {%0,%1,%2,%3},[%4];"
            : "=r"(af[kb][0]),"=r"(af[kb][1]),"=r"(af[kb][2]),"=r"(af[kb][3])
            : "r"(aAddr + kb*32));

    float acc[16][4];
    #pragma unroll
    for (int t=0;t<16;t++){ acc[t][0]=0.f; acc[t][1]=0.f; acc[t][2]=0.f; acc[t][3]=0.f; }

    #pragma unroll
    for (int tp=0; tp<8; tp++) {
        #pragma unroll
        for (int kb=0; kb<KT; kb++) {
            uint32_t b0,b1,b2,b3;
            asm volatile("ldmatrix.sync.aligned.m8n8.x4.trans.shared.b16 {%0,%1,%2,%3},[%4];"
                : "=r"(b0),"=r"(b1),"=r"(b2),"=r"(b3)
                : "r"(wBase + (uint32_t)((kb*16*PB + 16*tp)*2)));
            asm volatile("mma.sync.aligned.m16n8k16.row.col.f32.bf16.bf16.f32 "
                "{%0,%1,%2,%3},{%4,%5,%6,%7},{%8,%9},{%0,%1,%2,%3};"
                : "+f"(acc[2*tp][0]),"+f"(acc[2*tp][1]),"+f"(acc[2*tp][2]),"+f"(acc[2*tp][3])
                : "r"(af[kb][0]),"r"(af[kb][1]),"r"(af[kb][2]),"r"(af[kb][3]),"r"(b0),"r"(b1));
            asm volatile("mma.sync.aligned.m16n8k16.row.col.f32.bf16.bf16.f32 "
                "{%0,%1,%2,%3},{%4,%5,%6,%7},{%8,%9},{%0,%1,%2,%3};"
                : "+f"(acc[2*tp+1][0]),"+f"(acc[2*tp+1][1]),"+f"(acc[2*tp+1][2]),"+f"(acc[2*tp+1][3])
                : "r"(af[kb][0]),"r"(af[kb][1]),"r"(af[kb][2]),"r"(af[kb][3]),"r"(b2),"r"(b3));
        }
    }

    const int g  = lane >> 2;
    const int c4 = lane & 3;
    const int r0 = warp*16 + g;
    #pragma unroll
    for (int t=0;t<16;t++) {
        int col = t*8 + c4*2;
        float2 bb = *(const float2*)(bias + col);
        float v0 = acc[t][0] + bb.x;
        float v1 = acc[t][1] + bb.y;
        float v2 = acc[t][2] + bb.x;
        float v3 = acc[t][3] + bb.y;
        if (ACT) { v0 = gelu_f(v0); v1 = gelu_f(v1); v2 = gelu_f(v2); v3 = gelu_f(v3); }
        *(__nv_bfloat162*)(A + r0*PB + col)     = __floats2bfloat162_rn(v0, v1);
        *(__nv_bfloat162*)(A + (r0+8)*PB + col) = __floats2bfloat162_rn(v2, v3);
    }
    __syncwarp();
}

__global__ void __launch_bounds__(NTHREADS, 1)
fproj_kernel(const float* __restrict__ Fg,
             const float* __restrict__ latw,
             const float* __restrict__ W1, const float* __restrict__ b1,
             const float* __restrict__ W2, const float* __restrict__ b2,
             const float* __restrict__ W3, const float* __restrict__ b3,
             const float* __restrict__ W4, const float* __restrict__ b4,
             const float* __restrict__ W5, const float* __restrict__ b5,
             const int* __restrict__ traj,
             float* __restrict__ out, int n, int ntiles)
{
    extern __shared__ __align__(16) unsigned char smraw[];
    __nv_bfloat16* A0  = (__nv_bfloat16*)(smraw + OFF_A0);
    __nv_bfloat16* W1s = (__nv_bfloat16*)(smraw + OFF_W1);
    __nv_bfloat16* W2s = (__nv_bfloat16*)(smraw + OFF_W2);
    __nv_bfloat16* W3s = (__nv_bfloat16*)(smraw + OFF_W3);
    __nv_bfloat16* W4s = (__nv_bfloat16*)(smraw + OFF_W4);
    float*         W5s = (float*)(smraw + OFF_W5);
    float*         bsm = (float*)(smraw + OFF_BIAS);
    float*         Fsm = (float*)(smraw + OFF_F);
    float*         Rsm = (float*)(smraw + OFF_R);

    const int tid = threadIdx.x;

    // ---- one-time weight staging (all 512 threads) ----
    stage_w(W1, W1s, INDIM, tid, NTHREADS);
    for (int i = tid; i < 2*HID; i += NTHREADS) {            // zero-pad W1 rows 94,95
        int k = INDIM + (i >> 7), nn = i & 127;
        W1s[k*PB + nn] = __float2bfloat16(0.0f);
    }
    stage_w(W2, W2s, HID, tid, NTHREADS);
    stage_w(W3, W3s, HID, tid, NTHREADS);
    stage_w(W4, W4s, HID, tid, NTHREADS);
    for (int i = tid; i < HID*9; i += NTHREADS) W5s[i] = W5[i];
    if (tid < HID)      bsm[tid]       = b1[tid];
    else if (tid < 2*HID) bsm[tid]     = b2[tid-HID];
    else if (tid < 3*HID) bsm[tid]     = b3[tid-2*HID];
    else if (tid < 4*HID) bsm[tid]     = b4[tid-3*HID];
    if (tid < 9) bsm[4*HID + tid] = b5[tid];
    const float* latp = latw + (size_t)traj[0] * 64;
    __syncthreads();

    // ---- persistent tile loop ----
    for (int tile = blockIdx.x; tile < ntiles; tile += gridDim.x) {
        const int base = tile * ROWS;

        // Phase 1: threads 0-255 -> SVD + input assembly for row (base+tid)
        if (tid < ROWS) {
            int r = base + tid;
            __nv_bfloat16* invp = A0 + tid*PB;
            if (r < n) {
                const float* fp = Fg + (size_t)r*9;
                float f[9];
                #pragma unroll
                for (int i=0;i<9;i++) f[i] = fp[i];

                float S[3][3];
                #pragma unroll
                for (int i=0;i<3;i++)
                    #pragma unroll
                    for (int j=0;j<3;j++)
                        S[i][j] = f[0+i]*f[0+j] + f[3+i]*f[3+j] + f[6+i]*f[6+j];

                float V[3][3] = {{1,0,0},{0,1,0},{0,0,1}};
                #pragma unroll
                for (int sw=0; sw<6; sw++) { jrot2<0,1>(S,V); jrot2<0,2>(S,V); jrot2<1,2>(S,V); }

                float e[3] = {S[0][0], S[1][1], S[2][2]};
                cswap<0,1>(e,V); cswap<0,2>(e,V); cswap<1,2>(e,V);
                signfix<0>(V); signfix<1>(V); signfix<2>(V);

                float sig[3];
                #pragma unroll
                for (int j=0;j<3;j++) sig[j] = sqrtf(fmaxf(e[j], 0.0f));

                float U[3][3];
                #pragma unroll
                for (int j=0;j<3;j++) {
                    float inv_s = 1.0f / sig[j];
                    #pragma unroll
                    for (int i=0;i<3;i++)
                        U[i][j] = (f[3*i+0]*V[0][j] + f[3*i+1]*V[1][j] + f[3*i+2]*V[2][j]) * inv_s;
                }

                float R[9];
                #pragma unroll
                for (int i=0;i<3;i++)
                    #pragma unroll
                    for (int j=0;j<3;j++)
                        R[3*i+j] = U[i][0]*V[j][0] + U[i][1]*V[j][1] + U[i][2]*V[j][2];

                #pragma unroll
                for (int i=0;i<9;i++) invp[i] = __float2bfloat16(f[i]);
                #pragma unroll
                for (int i=0;i<3;i++)
                    #pragma unroll
                    for (int j=0;j<3;j++) invp[9 + 3*i + j] = __float2bfloat16(U[i][j]);
                #pragma unroll
                for (int i=0;i<3;i++) invp[18+i] = __float2bfloat16(sig[i]);
                #pragma unroll
                for (int i=0;i<3;i++)
                    #pragma unroll
                    for (int j=0;j<3;j++) invp[21 + 3*i + j] = __float2bfloat16(V[j][i]);
                #pragma unroll 8
                for (int c=0;c<64;c++) invp[30+c] = __float2bfloat16(latp[c]);
                invp[94] = __float2bfloat16(0.0f);
                invp[95] = __float2bfloat16(0.0f);

                #pragma unroll
                for (int i=0;i<9;i++) { Fsm[tid*9+i] = f[i]; Rsm[tid*9+i] = R[i]; }
            } else {
                for (int i=0;i<K1PAD;i++) invp[i] = __float2bfloat16(0.0f);
            }
        }
        __syncthreads();

        // Layers 1-4: barrier-free (in-place, warp-private rows)
        gemm_mma<6, true>(A0, W1s, bsm);
        gemm_mma<8, true>(A0, W2s, bsm + HID);
        gemm_mma<8, true>(A0, W3s, bsm + 2*HID);
        gemm_mma<8, true>(A0, W4s, bsm + 3*HID);
        __syncthreads();

        // Layer 5 + symmetrize + R*x + F epilogue (thread t -> row t)
        if (tid < ROWS) {
            int r = base + tid;
            if (r < n) {
                const __nv_bfloat16* h = A0 + tid*PB;
                const float* b5s = bsm + 4*HID;
                float x[9];
                #pragma unroll
                for (int j=0;j<9;j++) x[j] = b5s[j];
                #pragma unroll 4
                for (int k2=0;k2<HID/2;k2++) {
                    __nv_bfloat162 hv = *(const __nv_bfloat162*)(h + 2*k2);
                    float a0 = __bfloat162float(hv.x);
                    float a1 = __bfloat162float(hv.y);
                    const float* w0 = W5s + (2*k2)*9;
                    #pragma unroll
                    for (int j=0;j<9;j++) x[j] = fmaf(a0, w0[j], x[j]);
                    #pragma unroll
                    for (int j=0;j<9;j++) x[j] = fmaf(a1, w0[9+j], x[j]);
                }
                float xs[9];
                #pragma unroll
                for (int i=0;i<3;i++)
                    #pragma unroll
                    for (int j=0;j<3;j++)
                        xs[3*i+j] = 0.5f*(x[3*i+j] + x[3*j+i]);

                const float* R  = Rsm + tid*9;
                const float* Ff = Fsm + tid*9;
                float* op = out + (size_t)r*9;
                #pragma unroll
                for (int i=0;i<3;i++)
                    #pragma unroll
                    for (int j=0;j<3;j++)
                        op[3*i+j] = ALPHA_C*(R[3*i+0]*xs[0+j] + R[3*i+1]*xs[3+j] + R[3*i+2]*xs[6+j])
                                    + Ff[3*i+j];
            }
        }
        // no barrier needed: rows/F/R are thread-private between epilogue and next phase-1;
        // post-phase-1 barrier protects the GEMM reads.
    }
}

extern "C" void kernel_launch(void* const* d_in, const int* in_sizes, int n_in,
                              void* d_out, int out_size)
{
    const float* F    = (const float*)d_in[0];
    const float* latw = (const float*)d_in[1];
    const float* W1   = (const float*)d_in[2];
    const float* b1   = (const float*)d_in[3];
    const float* W2   = (const float*)d_in[4];
    const float* b2   = (const float*)d_in[5];
    const float* W3   = (const float*)d_in[6];
    const float* b3   = (const float*)d_in[7];
    const float* W4   = (const float*)d_in[8];
    const float* b4   = (const float*)d_in[9];
    const float* W5   = (const float*)d_in[10];
    const float* b5   = (const float*)d_in[11];
    const int*   traj = (const int*)d_in[12];
    float* out = (float*)d_out;

    int n = in_sizes[0] / 9;
    int ntiles = (n + ROWS - 1) / ROWS;

    int sms = 148;
    cudaDeviceGetAttribute(&sms, cudaDevAttrMultiProcessorCount, 0);
    int grid = sms < ntiles ? sms : ntiles;

    cudaFuncSetAttribute(fproj_kernel, cudaFuncAttributeMaxDynamicSharedMemorySize, SMEM_BYTES);
    fproj_kernel<<<grid, NTHREADS, SMEM_BYTES>>>(F, latw, W1,b1, W2,b2, W3,b3, W4,b4, W5,b5,
                                                 traj, out, n, ntiles);
}